// round 3
// baseline (speedup 1.0000x reference)
#include <cuda_runtime.h>
#include <math.h>

#define NV   8192
#define DV   256
#define NEGF (-1000000000.0f)

// Scratch (allocation-free rule: __device__ globals)
__device__ float g_Wh[NV * DV];       // 8 MB, L2-resident during k_attn
__device__ float g_f[NV];
__device__ float g_m[NV];
__device__ float g_is[NV];            // 1/sum
__device__ float g_elu_scratch[NV * DV]; // fallback if d_out holds alpha only

__device__ __forceinline__ float lk(float x) { return x > 0.f ? x : 0.2f * x; }
__device__ __forceinline__ float elu_f(float x) { return x > 0.f ? x : expm1f(x); }

// ---------------------------------------------------------------------------
// Kernel 1: Wh = h @ W   (M=8192, N=256, K=256), 64-row x 256-col block tile
// ---------------------------------------------------------------------------
__global__ __launch_bounds__(256) void k_gemm_wh(const float* __restrict__ h,
                                                 const float* __restrict__ W) {
    __shared__ float hS[64][33];     // K-step 32, pad 33 -> conflict-free reads
    __shared__ float wS[32][256];
    const int tid = threadIdx.x;
    const int tx = tid & 15, ty = tid >> 4;
    const int r0 = blockIdx.x * 64;

    float acc[4][4][4];
#pragma unroll
    for (int v = 0; v < 4; v++)
#pragma unroll
        for (int g = 0; g < 4; g++)
#pragma unroll
            for (int u = 0; u < 4; u++) acc[v][g][u] = 0.f;

    for (int kb = 0; kb < DV; kb += 32) {
        // h tile: 64x32 = 512 float4
#pragma unroll
        for (int q = 0; q < 2; q++) {
            int lin = q * 256 + tid;
            int r = lin >> 3, c4 = (lin & 7) * 4;
            float4 v = *(const float4*)&h[(size_t)(r0 + r) * DV + kb + c4];
            hS[r][c4] = v.x; hS[r][c4 + 1] = v.y; hS[r][c4 + 2] = v.z; hS[r][c4 + 3] = v.w;
        }
        // W tile: 32x256 = 2048 float4
#pragma unroll
        for (int q = 0; q < 8; q++) {
            int lin = q * 256 + tid;
            int k = lin >> 6, c4 = (lin & 63) * 4;
            *(float4*)&wS[k][c4] = *(const float4*)&W[(size_t)(kb + k) * DV + c4];
        }
        __syncthreads();
#pragma unroll 8
        for (int k = 0; k < 32; k++) {
            float av[4];
#pragma unroll
            for (int v = 0; v < 4; v++) av[v] = hS[ty * 4 + v][k];
#pragma unroll
            for (int g = 0; g < 4; g++) {
                float4 w = *(float4*)&wS[k][g * 64 + tx * 4];
#pragma unroll
                for (int v = 0; v < 4; v++) {
                    acc[v][g][0] += av[v] * w.x;
                    acc[v][g][1] += av[v] * w.y;
                    acc[v][g][2] += av[v] * w.z;
                    acc[v][g][3] += av[v] * w.w;
                }
            }
        }
        __syncthreads();
    }
#pragma unroll
    for (int v = 0; v < 4; v++)
#pragma unroll
        for (int g = 0; g < 4; g++) {
            float4 r = make_float4(acc[v][g][0], acc[v][g][1], acc[v][g][2], acc[v][g][3]);
            *(float4*)&g_Wh[(size_t)(r0 + ty * 4 + v) * DV + g * 64 + tx * 4] = r;
        }
}

// ---------------------------------------------------------------------------
// Kernel 2: f = Wh @ a    (one warp per row)
// ---------------------------------------------------------------------------
__global__ __launch_bounds__(256) void k_f(const float* __restrict__ a) {
    const int warp = threadIdx.x >> 5, lane = threadIdx.x & 31;
    const int row = blockIdx.x * 8 + warp;
    const float4* wr = (const float4*)&g_Wh[(size_t)row * DV];
    const float4* a4 = (const float4*)a;
    float s = 0.f;
#pragma unroll
    for (int i = 0; i < 2; i++) {
        float4 w = wr[lane * 2 + i];
        float4 av = __ldg(&a4[lane * 2 + i]);
        s += w.x * av.x + w.y * av.y + w.z * av.z + w.w * av.w;
    }
#pragma unroll
    for (int off = 16; off; off >>= 1) s += __shfl_xor_sync(0xffffffffu, s, off);
    if (lane == 0) g_f[row] = s;
}

// ---------------------------------------------------------------------------
// Kernel 3 (pass A): per-row softmax stats m_i, 1/s_i over masked leaky scores
// Uniform formula: x = adj>0 ? leaky(f_i+f_j) : -1e9 (matches reference exactly,
// including fully-masked rows). 4 rows per block.
// ---------------------------------------------------------------------------
__global__ __launch_bounds__(256) void k_rowstats(const int* __restrict__ adj) {
    __shared__ float mS[256], sS[256];
    const int tid = threadIdx.x;
    for (int rr = 0; rr < 4; rr++) {
        const int row = blockIdx.x * 4 + rr;
        const float fi = g_f[row];
        const int4* ar = (const int4*)(adj + (size_t)row * NV);
        const float4* f4 = (const float4*)g_f;
        float m = -3.0e38f, s = 0.f;
#pragma unroll
        for (int q = 0; q < 8; q++) {
            int idx = q * 256 + tid;
            int4 ad = __ldg(&ar[idx]);
            float4 fj = __ldg(&f4[idx]);
            float x0 = ad.x > 0 ? lk(fi + fj.x) : NEGF;
            float x1 = ad.y > 0 ? lk(fi + fj.y) : NEGF;
            float x2 = ad.z > 0 ? lk(fi + fj.z) : NEGF;
            float x3 = ad.w > 0 ? lk(fi + fj.w) : NEGF;
            float mx = fmaxf(fmaxf(x0, x1), fmaxf(x2, x3));
            float nm = fmaxf(m, mx);
            s = s * __expf(m - nm) + __expf(x0 - nm) + __expf(x1 - nm)
              + __expf(x2 - nm) + __expf(x3 - nm);
            m = nm;
        }
        mS[tid] = m; sS[tid] = s;
        __syncthreads();
        for (int off = 128; off; off >>= 1) {
            if (tid < off) {
                float m1 = mS[tid], s1 = sS[tid];
                float m2 = mS[tid + off], s2 = sS[tid + off];
                float nm = fmaxf(m1, m2);
                mS[tid] = nm;
                sS[tid] = s1 * __expf(m1 - nm) + s2 * __expf(m2 - nm);
            }
            __syncthreads();
        }
        if (tid == 0) { g_m[row] = mS[0]; g_is[row] = 1.f / sS[0]; }
        __syncthreads();
    }
}

// ---------------------------------------------------------------------------
// Kernel 4 (pass B): per 64-row x 128-col output tile, loop K=8192 in steps
// of 32: recompute alpha tile in SMEM (write to gmem from col-block 0 only),
// then register-tiled fp32 MMA  h' += alpha_tile @ Wh_tile. Fused elu epilogue.
// grid = (2 col-halves, 128 row-tiles) = 256 blocks.
// ---------------------------------------------------------------------------
__global__ __launch_bounds__(256) void k_attn(const int* __restrict__ adj,
                                              float* __restrict__ out_elu,
                                              float* __restrict__ out_alpha) {
    __shared__ float aS[64][33];
    __shared__ float wS[32][128];
    __shared__ float frS[64], mSr[64], isS[64];
    const int tid = threadIdx.x;
    const int tx = tid & 15, ty = tid >> 4;
    const int r0 = blockIdx.y * 64;
    const int cb = blockIdx.x * 128;
    const bool writeA = (blockIdx.x == 0) && (out_alpha != nullptr);

    if (tid < 64) {
        frS[tid] = g_f[r0 + tid];
        mSr[tid] = g_m[r0 + tid];
        isS[tid] = g_is[r0 + tid];
    }
    float acc[4][2][4];
#pragma unroll
    for (int v = 0; v < 4; v++)
#pragma unroll
        for (int g = 0; g < 2; g++)
#pragma unroll
            for (int u = 0; u < 4; u++) acc[v][g][u] = 0.f;
    __syncthreads();

    for (int kb = 0; kb < NV; kb += 32) {
        // alpha tile 64x32: 512 int4 of adj
#pragma unroll
        for (int q = 0; q < 2; q++) {
            int lin = q * 256 + tid;
            int r = lin >> 3, c4 = (lin & 7) * 4;
            int4 ad = __ldg((const int4*)&adj[(size_t)(r0 + r) * NV + kb + c4]);
            float4 fj = __ldg((const float4*)&g_f[kb + c4]);
            float fi = frS[r], mm = mSr[r], is = isS[r];
            float4 al;
            al.x = __expf(((ad.x > 0) ? lk(fi + fj.x) : NEGF) - mm) * is;
            al.y = __expf(((ad.y > 0) ? lk(fi + fj.y) : NEGF) - mm) * is;
            al.z = __expf(((ad.z > 0) ? lk(fi + fj.z) : NEGF) - mm) * is;
            al.w = __expf(((ad.w > 0) ? lk(fi + fj.w) : NEGF) - mm) * is;
            aS[r][c4] = al.x; aS[r][c4 + 1] = al.y; aS[r][c4 + 2] = al.z; aS[r][c4 + 3] = al.w;
            if (writeA)
                *(float4*)&out_alpha[(size_t)(r0 + r) * NV + kb + c4] = al;
        }
        // Wh tile 32x128: 1024 float4 (L2-resident)
#pragma unroll
        for (int q = 0; q < 4; q++) {
            int lin = q * 256 + tid;
            int k = lin >> 5, c4 = (lin & 31) * 4;
            *(float4*)&wS[k][c4] = __ldg((const float4*)&g_Wh[(size_t)(kb + k) * DV + cb + c4]);
        }
        __syncthreads();
#pragma unroll 16
        for (int k = 0; k < 32; k++) {
            float av[4];
#pragma unroll
            for (int v = 0; v < 4; v++) av[v] = aS[ty * 4 + v][k];
            float4 w0 = *(float4*)&wS[k][tx * 4];
            float4 w1 = *(float4*)&wS[k][64 + tx * 4];
#pragma unroll
            for (int v = 0; v < 4; v++) {
                acc[v][0][0] += av[v] * w0.x;
                acc[v][0][1] += av[v] * w0.y;
                acc[v][0][2] += av[v] * w0.z;
                acc[v][0][3] += av[v] * w0.w;
                acc[v][1][0] += av[v] * w1.x;
                acc[v][1][1] += av[v] * w1.y;
                acc[v][1][2] += av[v] * w1.z;
                acc[v][1][3] += av[v] * w1.w;
            }
        }
        __syncthreads();
    }

    float* oe = out_elu ? out_elu : g_elu_scratch;
#pragma unroll
    for (int v = 0; v < 4; v++)
#pragma unroll
        for (int g = 0; g < 2; g++) {
            float4 r;
            r.x = elu_f(acc[v][g][0]);
            r.y = elu_f(acc[v][g][1]);
            r.z = elu_f(acc[v][g][2]);
            r.w = elu_f(acc[v][g][3]);
            *(float4*)&oe[(size_t)(r0 + ty * 4 + v) * DV + cb + g * 64 + tx * 4] = r;
        }
}

// ---------------------------------------------------------------------------
extern "C" void kernel_launch(void* const* d_in, const int* in_sizes, int n_in,
                              void* d_out, int out_size) {
    const float* h  = (const float*)d_in[0];
    const int*   adj = (const int*)d_in[1];
    const float* W  = (const float*)d_in[2];
    const float* a  = (const float*)d_in[3];
    float* out = (float*)d_out;

    const long long elu_n = (long long)NV * DV;       // 2,097,152
    const long long alp_n = (long long)NV * NV;       // 67,108,864

    float* out_elu;
    float* out_alpha;
    if ((long long)out_size >= elu_n + alp_n) {       // tuple concat: (elu, alpha)
        out_elu = out;
        out_alpha = out + elu_n;
    } else if ((long long)out_size == alp_n) {        // alpha only
        out_elu = nullptr;                            // kernel falls back to scratch
        out_alpha = out;
    } else {                                          // elu only
        out_elu = out;
        out_alpha = nullptr;
    }

    k_gemm_wh<<<NV / 64, 256>>>(h, W);
    k_f<<<NV / 8, 256>>>(a);
    k_rowstats<<<NV / 4, 256>>>(adj);
    dim3 gB(2, NV / 64);
    k_attn<<<gB, 256>>>(adj, out_elu, out_alpha);
}

// round 5
// speedup vs baseline: 2.6193x; 2.6193x over previous
#include <cuda_runtime.h>
#include <cstdint>
#include <math.h>

#define NV 8192
#define DV 256

// ---------------- device scratch (allocation-free rule) ----------------
__device__ float    g_Wht[NV * DV];     // Wh, tf32-rounded fp32 (B operand)
__device__ float    g_f[NV];
__device__ float    g_u[NV];            // exp(f)
__device__ float    g_v[NV];            // exp(0.2 f)
__device__ float    g_c[NV];            // u/s
__device__ float    g_d[NV];            // v/s
__device__ unsigned g_bm[NV * 256];     // adjacency bitmask
__device__ float    g_part[2 * NV * DV];
__device__ float    g_elu_scratch[NV * DV];

__device__ __forceinline__ float elu_f(float x) { return x > 0.f ? x : expm1f(x); }
__device__ __forceinline__ uint32_t tf32r(float x) {
    uint32_t r; asm("cvt.rna.tf32.f32 %0, %1;" : "=r"(r) : "f"(x)); return r;
}
__device__ __forceinline__ void mma_tf32(float* d, const uint32_t* a, const uint32_t* b) {
    asm volatile("mma.sync.aligned.m16n8k8.row.col.f32.tf32.tf32.f32 "
        "{%0,%1,%2,%3},{%4,%5,%6,%7},{%8,%9},{%0,%1,%2,%3};"
        : "+f"(d[0]), "+f"(d[1]), "+f"(d[2]), "+f"(d[3])
        : "r"(a[0]), "r"(a[1]), "r"(a[2]), "r"(a[3]), "r"(b[0]), "r"(b[1]));
}

// ---------------------------------------------------------------------------
// Kernel 1: Wh = h@W (fp32). Epilogue: f=Wh@a, u=exp(f), v=exp(0.2f),
// g_Wht = tf32-rounded Wh.
// ---------------------------------------------------------------------------
__global__ __launch_bounds__(256) void k_gemm_wh(const float* __restrict__ h,
                                                 const float* __restrict__ W,
                                                 const float* __restrict__ a) {
    __shared__ float hS[64][33];
    __shared__ float wS[32][256];
    const int tid = threadIdx.x;
    const int tx = tid & 15, ty = tid >> 4;
    const int r0 = blockIdx.x * 64;

    float acc[4][4][4];
#pragma unroll
    for (int v = 0; v < 4; v++)
#pragma unroll
        for (int g = 0; g < 4; g++)
#pragma unroll
            for (int u = 0; u < 4; u++) acc[v][g][u] = 0.f;

    for (int kb = 0; kb < DV; kb += 32) {
#pragma unroll
        for (int q = 0; q < 2; q++) {
            int lin = q * 256 + tid;
            int r = lin >> 3, c4 = (lin & 7) * 4;
            float4 v = *(const float4*)&h[(size_t)(r0 + r) * DV + kb + c4];
            hS[r][c4] = v.x; hS[r][c4 + 1] = v.y; hS[r][c4 + 2] = v.z; hS[r][c4 + 3] = v.w;
        }
#pragma unroll
        for (int q = 0; q < 8; q++) {
            int lin = q * 256 + tid;
            int k = lin >> 6, c4 = (lin & 63) * 4;
            *(float4*)&wS[k][c4] = *(const float4*)&W[(size_t)(kb + k) * DV + c4];
        }
        __syncthreads();
#pragma unroll 8
        for (int k = 0; k < 32; k++) {
            float av[4];
#pragma unroll
            for (int v = 0; v < 4; v++) av[v] = hS[ty * 4 + v][k];
#pragma unroll
            for (int g = 0; g < 4; g++) {
                float4 w = *(float4*)&wS[k][g * 64 + tx * 4];
#pragma unroll
                for (int v = 0; v < 4; v++) {
                    acc[v][g][0] += av[v] * w.x;
                    acc[v][g][1] += av[v] * w.y;
                    acc[v][g][2] += av[v] * w.z;
                    acc[v][g][3] += av[v] * w.w;
                }
            }
        }
        __syncthreads();
    }

    // f = Wh @ a  (reduce across the 16 tx lanes)
    float fp[4] = {0.f, 0.f, 0.f, 0.f};
#pragma unroll
    for (int g = 0; g < 4; g++)
#pragma unroll
        for (int u = 0; u < 4; u++) {
            float av = __ldg(&a[g * 64 + tx * 4 + u]);
#pragma unroll
            for (int v = 0; v < 4; v++) fp[v] += acc[v][g][u] * av;
        }
#pragma unroll
    for (int v = 0; v < 4; v++) {
#pragma unroll
        for (int m = 1; m < 16; m <<= 1) fp[v] += __shfl_xor_sync(0xffffffffu, fp[v], m);
        if (tx == 0) {
            int row = r0 + ty * 4 + v;
            g_f[row] = fp[v];
            g_u[row] = __expf(fp[v]);
            g_v[row] = __expf(0.2f * fp[v]);
        }
    }

    // g_Wht tf32-rounded
#pragma unroll
    for (int v = 0; v < 4; v++)
#pragma unroll
        for (int g = 0; g < 4; g++) {
            float4 r;
            r.x = __uint_as_float(tf32r(acc[v][g][0]));
            r.y = __uint_as_float(tf32r(acc[v][g][1]));
            r.z = __uint_as_float(tf32r(acc[v][g][2]));
            r.w = __uint_as_float(tf32r(acc[v][g][3]));
            *(float4*)&g_Wht[(size_t)(r0 + ty * 4 + v) * DV + g * 64 + tx * 4] = r;
        }
}

// ---------------------------------------------------------------------------
// Kernel 2: bitmask + rowsum (separable, no exp). One block per row.
// s_i = u_i * sum_{mask,u_j>1/u_i} u_j + v_i * sum_{mask,else} v_j
// ---------------------------------------------------------------------------
__global__ __launch_bounds__(256) void k_prep(const int* __restrict__ adj) {
    const int row = blockIdx.x;
    const int wid = threadIdx.x >> 5, lane = threadIdx.x & 31;
    const float ui = __ldg(&g_u[row]);
    const float vi = __ldg(&g_v[row]);
    const float th = 1.f / ui;
    const int4* ar = (const int4*)(adj + (size_t)row * NV);
    const float4* u4p = (const float4*)g_u;
    const float4* v4p = (const float4*)g_v;

    float su = 0.f, sv = 0.f;
#pragma unroll
    for (int it = 0; it < 8; it++) {
        int idx4 = wid * 256 + it * 32 + lane;
        int4   ad = __ldg(&ar[idx4]);
        float4 u4 = __ldg(&u4p[idx4]);
        float4 v4 = __ldg(&v4p[idx4]);
        uint32_t nib = 0;
        {
            bool m0 = ad.x > 0, m1 = ad.y > 0, m2 = ad.z > 0, m3 = ad.w > 0;
            nib = (m0 ? 1u : 0u) | (m1 ? 2u : 0u) | (m2 ? 4u : 0u) | (m3 ? 8u : 0u);
            bool p0 = u4.x > th, p1 = u4.y > th, p2 = u4.z > th, p3 = u4.w > th;
            su += (m0 && p0) ? u4.x : 0.f;  sv += (m0 && !p0) ? v4.x : 0.f;
            su += (m1 && p1) ? u4.y : 0.f;  sv += (m1 && !p1) ? v4.y : 0.f;
            su += (m2 && p2) ? u4.z : 0.f;  sv += (m2 && !p2) ? v4.z : 0.f;
            su += (m3 && p3) ? u4.w : 0.f;  sv += (m3 && !p3) ? v4.w : 0.f;
        }
        // pack nibbles (lane-major, 4 bits each) into 32-bit words
        uint32_t o = __shfl_xor_sync(0xffffffffu, nib, 1);
        uint32_t byt = (lane & 1) ? (o | (nib << 4)) : (nib | (o << 4));
        o = __shfl_xor_sync(0xffffffffu, byt, 2);
        uint32_t hlf = (lane & 2) ? (o | (byt << 8)) : (byt | (o << 8));
        o = __shfl_xor_sync(0xffffffffu, hlf, 4);
        uint32_t wrd = (lane & 4) ? (o | (hlf << 16)) : (hlf | (o << 16));
        if ((lane & 7) == 0)
            g_bm[(size_t)row * 256 + wid * 32 + it * 4 + (lane >> 3)] = wrd;
    }
#pragma unroll
    for (int m = 16; m; m >>= 1) {
        su += __shfl_xor_sync(0xffffffffu, su, m);
        sv += __shfl_xor_sync(0xffffffffu, sv, m);
    }
    __shared__ float ssu[8], ssv[8];
    if (lane == 0) { ssu[wid] = su; ssv[wid] = sv; }
    __syncthreads();
    if (threadIdx.x == 0) {
        float tu = 0.f, tv = 0.f;
#pragma unroll
        for (int i = 0; i < 8; i++) { tu += ssu[i]; tv += ssv[i]; }
        float s = ui * tu + vi * tv;
        g_c[row] = ui / s;
        g_d[row] = vi / s;
    }
}

// ---------------------------------------------------------------------------
// Kernel 3: h' = alpha @ Wh via mma.sync tf32. CTA = 128 rows x 256 cols,
// split-K=2. Alpha built on the fly (exact fp32 -> gmem, tf32 -> SMEM).
// ---------------------------------------------------------------------------
#define SM_A 0                         // uint32 tf32 A [128][36]
#define SM_B (128 * 36 * 4)            // float B [32][264]
#define SM_C (SM_B + 32 * 264 * 4)
#define SM_D (SM_C + 512)
#define SM_T (SM_D + 512)
#define SMEM_TOTAL (SM_T + 512)        // 53760 B

__global__ __launch_bounds__(512) void k_attn(float* __restrict__ out_alpha) {
    extern __shared__ char sm[];
    uint32_t* sA = (uint32_t*)(sm + SM_A);
    float*    sB = (float*)(sm + SM_B);
    float*    sc = (float*)(sm + SM_C);
    float*    sd = (float*)(sm + SM_D);
    float*    st = (float*)(sm + SM_T);

    const int tid = threadIdx.x;
    const int wid = tid >> 5, lane = tid & 31;
    const int wm = wid >> 2, wn = wid & 3;            // 4x4 warps, tile 32x64
    const int kh = blockIdx.x, rt = blockIdx.y;
    const int r0 = rt * 128;
    const int br = tid >> 2, kq = (tid & 3) * 8;      // build coords
    const bool wA = (out_alpha != nullptr);

    if (tid < 128) {
        sc[tid] = g_c[r0 + tid];
        sd[tid] = g_d[r0 + tid];
        st[tid] = 1.f / g_u[r0 + tid];
    }
    float acc[2][8][4];
#pragma unroll
    for (int mt = 0; mt < 2; mt++)
#pragma unroll
        for (int nb = 0; nb < 8; nb++)
#pragma unroll
            for (int q = 0; q < 4; q++) acc[mt][nb][q] = 0.f;
    __syncthreads();

    for (int c = 0; c < 128; c++) {
        const int kb = kh * (NV / 2) + c * 32;
        // ---- B copy: rows kb..kb+31 of g_Wht into [32][264] ----
#pragma unroll
        for (int q = 0; q < 4; q++) {
            int idx = q * 512 + tid;
            int row = idx >> 6, col = (idx & 63) << 2;
            float4 w = __ldg((const float4*)&g_Wht[(size_t)(kb + row) * DV + col]);
            *(float4*)&sB[row * 264 + col] = w;
        }
        // ---- A build: 8 alpha elements per thread ----
        {
            uint32_t word = __ldg(&g_bm[(size_t)(r0 + br) * 256 + (kb >> 5)]);
            float ci = sc[br], di = sd[br], th = st[br];
            float4 u0 = __ldg((const float4*)&g_u[kb + kq]);
            float4 u1 = __ldg((const float4*)&g_u[kb + kq + 4]);
            float4 v0 = __ldg((const float4*)&g_v[kb + kq]);
            float4 v1 = __ldg((const float4*)&g_v[kb + kq + 4]);
            float av[8];
            const float ue[8] = {u0.x, u0.y, u0.z, u0.w, u1.x, u1.y, u1.z, u1.w};
            const float ve[8] = {v0.x, v0.y, v0.z, v0.w, v1.x, v1.y, v1.z, v1.w};
#pragma unroll
            for (int e = 0; e < 8; e++) {
                bool bit = (word >> (kq + e)) & 1u;
                float val = 0.f;
                if (bit) val = (ue[e] > th) ? ci * ue[e] : di * ve[e];
                av[e] = val;
            }
            if (wA) {
                float* dst = &out_alpha[(size_t)(r0 + br) * NV + kb + kq];
                *(float4*)dst       = make_float4(av[0], av[1], av[2], av[3]);
                *(float4*)(dst + 4) = make_float4(av[4], av[5], av[6], av[7]);
            }
            uint4 p0 = make_uint4(tf32r(av[0]), tf32r(av[1]), tf32r(av[2]), tf32r(av[3]));
            uint4 p1 = make_uint4(tf32r(av[4]), tf32r(av[5]), tf32r(av[6]), tf32r(av[7]));
            *(uint4*)&sA[br * 36 + kq]     = p0;
            *(uint4*)&sA[br * 36 + kq + 4] = p1;
        }
        __syncthreads();
        // ---- MMA: 4 k8 steps ----
#pragma unroll
        for (int kk = 0; kk < 4; kk++) {
            uint32_t afr[2][4];
#pragma unroll
            for (int mt = 0; mt < 2; mt++) {
                int r = wm * 32 + mt * 16 + (lane >> 2);
                int cc = kk * 8 + (lane & 3);
                afr[mt][0] = sA[r * 36 + cc];
                afr[mt][1] = sA[(r + 8) * 36 + cc];
                afr[mt][2] = sA[r * 36 + cc + 4];
                afr[mt][3] = sA[(r + 8) * 36 + cc + 4];
            }
#pragma unroll
            for (int nb = 0; nb < 8; nb++) {
                uint32_t bfr[2];
                int kr = kk * 8 + (lane & 3);
                int nc = wn * 64 + nb * 8 + (lane >> 2);
                bfr[0] = __float_as_uint(sB[kr * 264 + nc]);
                bfr[1] = __float_as_uint(sB[(kr + 4) * 264 + nc]);
                mma_tf32(acc[0][nb], afr[0], bfr);
                mma_tf32(acc[1][nb], afr[1], bfr);
            }
        }
        __syncthreads();
    }

    // ---- epilogue: split-K partials ----
#pragma unroll
    for (int mt = 0; mt < 2; mt++)
#pragma unroll
        for (int nb = 0; nb < 8; nb++) {
            int gr = r0 + wm * 32 + mt * 16 + (lane >> 2);
            int cl = wn * 64 + nb * 8 + (lane & 3) * 2;
            float* base = &g_part[((size_t)kh * NV + gr) * DV + cl];
            *(float2*)base            = make_float2(acc[mt][nb][0], acc[mt][nb][1]);
            *(float2*)(base + 8 * DV) = make_float2(acc[mt][nb][2], acc[mt][nb][3]);
        }
}

// ---------------------------------------------------------------------------
// Kernel 4: combine split-K partials + elu
// ---------------------------------------------------------------------------
__global__ __launch_bounds__(256) void k_combine(float* __restrict__ out_elu) {
    float* o = out_elu ? out_elu : g_elu_scratch;
    size_t i = ((size_t)blockIdx.x * 256 + threadIdx.x) * 4;
    float4 p0 = *(float4*)&g_part[i];
    float4 p1 = *(float4*)&g_part[(size_t)NV * DV + i];
    float4 r;
    r.x = elu_f(p0.x + p1.x);
    r.y = elu_f(p0.y + p1.y);
    r.z = elu_f(p0.z + p1.z);
    r.w = elu_f(p0.w + p1.w);
    *(float4*)&o[i] = r;
}

// ---------------------------------------------------------------------------
extern "C" void kernel_launch(void* const* d_in, const int* in_sizes, int n_in,
                              void* d_out, int out_size) {
    const float* h   = (const float*)d_in[0];
    const int*   adj = (const int*)d_in[1];
    const float* W   = (const float*)d_in[2];
    const float* a   = (const float*)d_in[3];
    float* out = (float*)d_out;

    const long long elu_n = (long long)NV * DV;
    const long long alp_n = (long long)NV * NV;
    float* out_elu;
    float* out_alpha;
    if ((long long)out_size >= elu_n + alp_n) { out_elu = out; out_alpha = out + elu_n; }
    else if ((long long)out_size == alp_n)    { out_elu = nullptr; out_alpha = out; }
    else                                      { out_elu = out; out_alpha = nullptr; }

    cudaFuncSetAttribute(k_attn, cudaFuncAttributeMaxDynamicSharedMemorySize, SMEM_TOTAL);

    k_gemm_wh<<<NV / 64, 256>>>(h, W, a);
    k_prep<<<NV, 256>>>(adj);
    dim3 gA(2, NV / 128);
    k_attn<<<gA, 512, SMEM_TOTAL>>>(out_alpha);
    k_combine<<<(unsigned)(elu_n / 4 / 256), 256>>>(out_elu);
}

// round 6
// speedup vs baseline: 2.6650x; 1.0174x over previous
#include <cuda_runtime.h>
#include <cstdint>
#include <math.h>

#define NV 8192
#define DV 256

// ---------------- device scratch (allocation-free rule) ----------------
__device__ float    g_Wht[NV * DV];     // Wh, tf32-rounded (B operand for k_attn)
__device__ float    g_wa[DV];           // W @ a
__device__ float    g_u[NV];            // exp(f)
__device__ float    g_v[NV];            // exp(0.2 f)
__device__ float    g_c[NV];            // u/s
__device__ float    g_d[NV];            // v/s
__device__ unsigned g_bm[NV * 256];     // adjacency bitmask
__device__ float    g_part[2 * NV * DV];
__device__ float    g_elu_scratch[NV * DV];

__device__ __forceinline__ float elu_f(float x) { return x > 0.f ? x : expm1f(x); }
__device__ __forceinline__ uint32_t tf32r(float x) {
    uint32_t r; asm("cvt.rna.tf32.f32 %0, %1;" : "=r"(r) : "f"(x)); return r;
}
__device__ __forceinline__ void mma_tf32(float* d, const uint32_t* a, const uint32_t* b) {
    asm volatile("mma.sync.aligned.m16n8k8.row.col.f32.tf32.tf32.f32 "
        "{%0,%1,%2,%3},{%4,%5,%6,%7},{%8,%9},{%0,%1,%2,%3};"
        : "+f"(d[0]), "+f"(d[1]), "+f"(d[2]), "+f"(d[3])
        : "r"(a[0]), "r"(a[1]), "r"(a[2]), "r"(a[3]), "r"(b[0]), "r"(b[1]));
}

// ---------------------------------------------------------------------------
// Kernel 0: wa = W @ a  (warp per row)
// ---------------------------------------------------------------------------
__global__ __launch_bounds__(256) void k_wa(const float* __restrict__ W,
                                            const float* __restrict__ a) {
    const int wid = threadIdx.x >> 5, lane = threadIdx.x & 31;
    const int row = blockIdx.x * 8 + wid;
    float s = 0.f;
#pragma unroll
    for (int i = 0; i < 2; i++) {
        float4 w = __ldg((const float4*)&W[row * DV + lane * 8 + i * 4]);
        float4 av = __ldg((const float4*)&a[lane * 8 + i * 4]);
        s += w.x * av.x + w.y * av.y + w.z * av.z + w.w * av.w;
    }
#pragma unroll
    for (int m = 16; m; m >>= 1) s += __shfl_xor_sync(0xffffffffu, s, m);
    if (lane == 0) g_wa[row] = s;
}

// ---------------------------------------------------------------------------
// Kernel 1: f = h @ wa (exact fp32), u = exp(f), v = exp(0.2 f). Warp per row.
// ---------------------------------------------------------------------------
__global__ __launch_bounds__(256) void k_f(const float* __restrict__ h) {
    const int wid = threadIdx.x >> 5, lane = threadIdx.x & 31;
    const int row = blockIdx.x * 8 + wid;
    float s = 0.f;
#pragma unroll
    for (int i = 0; i < 2; i++) {
        float4 w = __ldg((const float4*)&h[(size_t)row * DV + lane * 8 + i * 4]);
        float4 av = __ldg((const float4*)&g_wa[lane * 8 + i * 4]);
        s += w.x * av.x + w.y * av.y + w.z * av.z + w.w * av.w;
    }
#pragma unroll
    for (int m = 16; m; m >>= 1) s += __shfl_xor_sync(0xffffffffu, s, m);
    if (lane == 0) {
        g_u[row] = __expf(s);
        g_v[row] = __expf(0.2f * s);
    }
}

// ---------------------------------------------------------------------------
// Kernel 2: bitmask + rowsum (separable, no exp in O(N^2)). One block per row.
// ---------------------------------------------------------------------------
__global__ __launch_bounds__(256) void k_prep(const int* __restrict__ adj) {
    const int row = blockIdx.x;
    const int wid = threadIdx.x >> 5, lane = threadIdx.x & 31;
    const float ui = __ldg(&g_u[row]);
    const float vi = __ldg(&g_v[row]);
    const float th = 1.f / ui;
    const int4* ar = (const int4*)(adj + (size_t)row * NV);
    const float4* u4p = (const float4*)g_u;
    const float4* v4p = (const float4*)g_v;

    float su = 0.f, sv = 0.f;
#pragma unroll
    for (int it = 0; it < 8; it++) {
        int idx4 = wid * 256 + it * 32 + lane;
        int4   ad = __ldg(&ar[idx4]);
        float4 u4 = __ldg(&u4p[idx4]);
        float4 v4 = __ldg(&v4p[idx4]);
        bool m0 = ad.x > 0, m1 = ad.y > 0, m2 = ad.z > 0, m3 = ad.w > 0;
        uint32_t nib = (m0 ? 1u : 0u) | (m1 ? 2u : 0u) | (m2 ? 4u : 0u) | (m3 ? 8u : 0u);
        bool p0 = u4.x > th, p1 = u4.y > th, p2 = u4.z > th, p3 = u4.w > th;
        su += (m0 && p0) ? u4.x : 0.f;  sv += (m0 && !p0) ? v4.x : 0.f;
        su += (m1 && p1) ? u4.y : 0.f;  sv += (m1 && !p1) ? v4.y : 0.f;
        su += (m2 && p2) ? u4.z : 0.f;  sv += (m2 && !p2) ? v4.z : 0.f;
        su += (m3 && p3) ? u4.w : 0.f;  sv += (m3 && !p3) ? v4.w : 0.f;
        uint32_t o = __shfl_xor_sync(0xffffffffu, nib, 1);
        uint32_t byt = (lane & 1) ? (o | (nib << 4)) : (nib | (o << 4));
        o = __shfl_xor_sync(0xffffffffu, byt, 2);
        uint32_t hlf = (lane & 2) ? (o | (byt << 8)) : (byt | (o << 8));
        o = __shfl_xor_sync(0xffffffffu, hlf, 4);
        uint32_t wrd = (lane & 4) ? (o | (hlf << 16)) : (hlf | (o << 16));
        if ((lane & 7) == 0)
            g_bm[(size_t)row * 256 + wid * 32 + it * 4 + (lane >> 3)] = wrd;
    }
#pragma unroll
    for (int m = 16; m; m >>= 1) {
        su += __shfl_xor_sync(0xffffffffu, su, m);
        sv += __shfl_xor_sync(0xffffffffu, sv, m);
    }
    __shared__ float ssu[8], ssv[8];
    if (lane == 0) { ssu[wid] = su; ssv[wid] = sv; }
    __syncthreads();
    if (threadIdx.x == 0) {
        float tu = 0.f, tv = 0.f;
#pragma unroll
        for (int i = 0; i < 8; i++) { tu += ssu[i]; tv += ssv[i]; }
        float s = ui * tu + vi * tv;
        g_c[row] = ui / s;
        g_d[row] = vi / s;
    }
}

// ---------------------------------------------------------------------------
// Kernel 3: Wh = h @ W via tf32 mma. CTA = 128 rows x 256 cols, K=256.
// ---------------------------------------------------------------------------
#define WH_SMEM (128 * 36 * 4 + 32 * 264 * 4)   // 52224
__global__ __launch_bounds__(512) void k_wh_mma(const float* __restrict__ h,
                                                const float* __restrict__ W) {
    extern __shared__ char sm[];
    uint32_t* sA = (uint32_t*)sm;
    float*    sB = (float*)(sm + 128 * 36 * 4);
    const int tid = threadIdx.x;
    const int wid = tid >> 5, lane = tid & 31;
    const int wm = wid >> 2, wn = wid & 3;
    const int r0 = blockIdx.x * 128;
    const int br = tid >> 2, kq = (tid & 3) * 8;

    float acc[2][8][4];
#pragma unroll
    for (int mt = 0; mt < 2; mt++)
#pragma unroll
        for (int nb = 0; nb < 8; nb++)
#pragma unroll
            for (int q = 0; q < 4; q++) acc[mt][nb][q] = 0.f;

    for (int c = 0; c < 8; c++) {
        const int kb = c * 32;
        // A: h rows, tf32-rounded
        {
            float4 h0 = __ldg((const float4*)&h[(size_t)(r0 + br) * DV + kb + kq]);
            float4 h1 = __ldg((const float4*)&h[(size_t)(r0 + br) * DV + kb + kq + 4]);
            *(uint4*)&sA[br * 36 + kq]     = make_uint4(tf32r(h0.x), tf32r(h0.y), tf32r(h0.z), tf32r(h0.w));
            *(uint4*)&sA[br * 36 + kq + 4] = make_uint4(tf32r(h1.x), tf32r(h1.y), tf32r(h1.z), tf32r(h1.w));
        }
        // B: W rows, tf32-rounded
#pragma unroll
        for (int q = 0; q < 4; q++) {
            int idx = q * 512 + tid;
            int row = idx >> 6, col = (idx & 63) << 2;
            float4 w = __ldg((const float4*)&W[(size_t)(kb + row) * DV + col]);
            float4 t;
            t.x = __uint_as_float(tf32r(w.x)); t.y = __uint_as_float(tf32r(w.y));
            t.z = __uint_as_float(tf32r(w.z)); t.w = __uint_as_float(tf32r(w.w));
            *(float4*)&sB[row * 264 + col] = t;
        }
        __syncthreads();
#pragma unroll
        for (int kk = 0; kk < 4; kk++) {
            uint32_t afr[2][4];
#pragma unroll
            for (int mt = 0; mt < 2; mt++) {
                int r = wm * 32 + mt * 16 + (lane >> 2);
                int cc = kk * 8 + (lane & 3);
                afr[mt][0] = sA[r * 36 + cc];
                afr[mt][1] = sA[(r + 8) * 36 + cc];
                afr[mt][2] = sA[r * 36 + cc + 4];
                afr[mt][3] = sA[(r + 8) * 36 + cc + 4];
            }
#pragma unroll
            for (int nb = 0; nb < 8; nb++) {
                uint32_t bfr[2];
                int kr = kk * 8 + (lane & 3);
                int nc = wn * 64 + nb * 8 + (lane >> 2);
                bfr[0] = __float_as_uint(sB[kr * 264 + nc]);
                bfr[1] = __float_as_uint(sB[(kr + 4) * 264 + nc]);
                mma_tf32(acc[0][nb], afr[0], bfr);
                mma_tf32(acc[1][nb], afr[1], bfr);
            }
        }
        __syncthreads();
    }
    // epilogue: tf32-rounded Wh (consumed raw as tf32 by k_attn's B path)
#pragma unroll
    for (int mt = 0; mt < 2; mt++)
#pragma unroll
        for (int nb = 0; nb < 8; nb++) {
            int gr = r0 + wm * 32 + mt * 16 + (lane >> 2);
            int cl = wn * 64 + nb * 8 + (lane & 3) * 2;
            float* base = &g_Wht[(size_t)gr * DV + cl];
            base[0] = __uint_as_float(tf32r(acc[mt][nb][0]));
            base[1] = __uint_as_float(tf32r(acc[mt][nb][1]));
            base[8 * DV]     = __uint_as_float(tf32r(acc[mt][nb][2]));
            base[8 * DV + 1] = __uint_as_float(tf32r(acc[mt][nb][3]));
        }
}

// ---------------------------------------------------------------------------
// Kernel 4: h' = alpha @ Wh. Double-buffered software pipeline:
//   loads(c+1) -> mma(c) -> compute+store(c+1) -> sync
// ---------------------------------------------------------------------------
#define ST_A  (128 * 36 * 4)            // 18432
#define ST_B  (32 * 264 * 4)            // 33792
#define ST_SZ (ST_A + ST_B)             // 52224
#define AT_SMEM (2 * ST_SZ + 3 * 128 * 4)

struct Bld {
    uint32_t word;
    float4 u0, u1, v0, v1;
    float4 w[4];
};

__global__ __launch_bounds__(512) void k_attn(float* __restrict__ out_alpha) {
    extern __shared__ char sm[];
    uint32_t* sAs[2] = { (uint32_t*)sm, (uint32_t*)(sm + ST_SZ) };
    float*    sBs[2] = { (float*)(sm + ST_A), (float*)(sm + ST_SZ + ST_A) };
    float* sc  = (float*)(sm + 2 * ST_SZ);
    float* sd  = sc + 128;
    float* stt = sd + 128;

    const int tid = threadIdx.x;
    const int wid = tid >> 5, lane = tid & 31;
    const int wm = wid >> 2, wn = wid & 3;
    const int kh = blockIdx.x, rt = blockIdx.y;
    const int r0 = rt * 128;
    const int br = tid >> 2, kq = (tid & 3) * 8;
    const int bRow = (tid >> 6), bCol4 = (tid & 63) << 2;   // B-copy coords (q*512 offset)
    const bool wA = (out_alpha != nullptr);

    if (tid < 128) {
        sc[tid]  = g_c[r0 + tid];
        sd[tid]  = g_d[r0 + tid];
        stt[tid] = 1.f / g_u[r0 + tid];
    }
    float acc[2][8][4];
#pragma unroll
    for (int mt = 0; mt < 2; mt++)
#pragma unroll
        for (int nb = 0; nb < 8; nb++)
#pragma unroll
            for (int q = 0; q < 4; q++) acc[mt][nb][q] = 0.f;
    __syncthreads();

    // ---- helpers (inlined by compiler) ----
    auto build_loads = [&](int c, Bld& b) {
        const int kb = kh * (NV / 2) + c * 32;
        b.word = __ldg(&g_bm[(size_t)(r0 + br) * 256 + (kb >> 5)]);
        b.u0 = __ldg((const float4*)&g_u[kb + kq]);
        b.u1 = __ldg((const float4*)&g_u[kb + kq + 4]);
        b.v0 = __ldg((const float4*)&g_v[kb + kq]);
        b.v1 = __ldg((const float4*)&g_v[kb + kq + 4]);
#pragma unroll
        for (int q = 0; q < 4; q++) {
            int row = (q * 512 + tid) >> 6;
            b.w[q] = __ldg((const float4*)&g_Wht[(size_t)(kb + row) * DV + bCol4]);
        }
    };
    auto build_store = [&](int c, int s, const Bld& b) {
        const int kb = kh * (NV / 2) + c * 32;
        uint32_t* sA = sAs[s];
        float*    sB = sBs[s];
#pragma unroll
        for (int q = 0; q < 4; q++) {
            int row = (q * 512 + tid) >> 6;
            *(float4*)&sB[row * 264 + bCol4] = b.w[q];
        }
        float ci = sc[br], di = sd[br], th = stt[br];
        const float ue[8] = {b.u0.x, b.u0.y, b.u0.z, b.u0.w, b.u1.x, b.u1.y, b.u1.z, b.u1.w};
        const float ve[8] = {b.v0.x, b.v0.y, b.v0.z, b.v0.w, b.v1.x, b.v1.y, b.v1.z, b.v1.w};
        float av[8];
#pragma unroll
        for (int e = 0; e < 8; e++) {
            bool bit = (b.word >> (kq + e)) & 1u;
            av[e] = bit ? ((ue[e] > th) ? ci * ue[e] : di * ve[e]) : 0.f;
        }
        if (wA) {
            float* dst = &out_alpha[(size_t)(r0 + br) * NV + kb + kq];
            *(float4*)dst       = make_float4(av[0], av[1], av[2], av[3]);
            *(float4*)(dst + 4) = make_float4(av[4], av[5], av[6], av[7]);
        }
        *(uint4*)&sA[br * 36 + kq]     = make_uint4(tf32r(av[0]), tf32r(av[1]), tf32r(av[2]), tf32r(av[3]));
        *(uint4*)&sA[br * 36 + kq + 4] = make_uint4(tf32r(av[4]), tf32r(av[5]), tf32r(av[6]), tf32r(av[7]));
    };
    auto do_mma = [&](int s) {
        uint32_t* sA = sAs[s];
        float*    sB = sBs[s];
#pragma unroll
        for (int kk = 0; kk < 4; kk++) {
            uint32_t afr[2][4];
#pragma unroll
            for (int mt = 0; mt < 2; mt++) {
                int r = wm * 32 + mt * 16 + (lane >> 2);
                int cc = kk * 8 + (lane & 3);
                afr[mt][0] = sA[r * 36 + cc];
                afr[mt][1] = sA[(r + 8) * 36 + cc];
                afr[mt][2] = sA[r * 36 + cc + 4];
                afr[mt][3] = sA[(r + 8) * 36 + cc + 4];
            }
#pragma unroll
            for (int nb = 0; nb < 8; nb++) {
                uint32_t bfr[2];
                int kr = kk * 8 + (lane & 3);
                int nc = wn * 64 + nb * 8 + (lane >> 2);
                bfr[0] = __float_as_uint(sB[kr * 264 + nc]);
                bfr[1] = __float_as_uint(sB[(kr + 4) * 264 + nc]);
                mma_tf32(acc[0][nb], afr[0], bfr);
                mma_tf32(acc[1][nb], afr[1], bfr);
            }
        }
    };

    // ---- pipeline ----
    {
        Bld b0;
        build_loads(0, b0);
        build_store(0, 0, b0);
    }
    __syncthreads();
#pragma unroll 1
    for (int c = 0; c < 128; c++) {
        const int st = c & 1;
        Bld nb_;
        if (c < 127) build_loads(c + 1, nb_);
        do_mma(st);
        if (c < 127) build_store(c + 1, st ^ 1, nb_);
        __syncthreads();
    }

    // ---- epilogue: split-K partials ----
#pragma unroll
    for (int mt = 0; mt < 2; mt++)
#pragma unroll
        for (int nb = 0; nb < 8; nb++) {
            int gr = r0 + wm * 32 + mt * 16 + (lane >> 2);
            int cl = wn * 64 + nb * 8 + (lane & 3) * 2;
            float* base = &g_part[((size_t)kh * NV + gr) * DV + cl];
            *(float2*)base            = make_float2(acc[mt][nb][0], acc[mt][nb][1]);
            *(float2*)(base + 8 * DV) = make_float2(acc[mt][nb][2], acc[mt][nb][3]);
        }
}

// ---------------------------------------------------------------------------
// Kernel 5: combine split-K partials + elu
// ---------------------------------------------------------------------------
__global__ __launch_bounds__(256) void k_combine(float* __restrict__ out_elu) {
    float* o = out_elu ? out_elu : g_elu_scratch;
    size_t i = ((size_t)blockIdx.x * 256 + threadIdx.x) * 4;
    float4 p0 = *(float4*)&g_part[i];
    float4 p1 = *(float4*)&g_part[(size_t)NV * DV + i];
    float4 r;
    r.x = elu_f(p0.x + p1.x);
    r.y = elu_f(p0.y + p1.y);
    r.z = elu_f(p0.z + p1.z);
    r.w = elu_f(p0.w + p1.w);
    *(float4*)&o[i] = r;
}

// ---------------------------------------------------------------------------
extern "C" void kernel_launch(void* const* d_in, const int* in_sizes, int n_in,
                              void* d_out, int out_size) {
    const float* h   = (const float*)d_in[0];
    const int*   adj = (const int*)d_in[1];
    const float* W   = (const float*)d_in[2];
    const float* a   = (const float*)d_in[3];
    float* out = (float*)d_out;

    const long long elu_n = (long long)NV * DV;
    const long long alp_n = (long long)NV * NV;
    float* out_elu;
    float* out_alpha;
    if ((long long)out_size >= elu_n + alp_n) { out_elu = out; out_alpha = out + elu_n; }
    else if ((long long)out_size == alp_n)    { out_elu = nullptr; out_alpha = out; }
    else                                      { out_elu = out; out_alpha = nullptr; }

    cudaFuncSetAttribute(k_wh_mma, cudaFuncAttributeMaxDynamicSharedMemorySize, WH_SMEM);
    cudaFuncSetAttribute(k_attn,   cudaFuncAttributeMaxDynamicSharedMemorySize, AT_SMEM);

    k_wa<<<32, 256>>>(W, a);
    k_f<<<NV / 8, 256>>>(h);
    k_prep<<<NV, 256>>>(adj);
    k_wh_mma<<<NV / 128, 512, WH_SMEM>>>(h, W);
    dim3 gA(2, NV / 128);
    k_attn<<<gA, 512, AT_SMEM>>>(out_alpha);
    k_combine<<<(unsigned)(elu_n / 4 / 256), 256>>>(out_elu);
}